// round 14
// baseline (speedup 1.0000x reference)
#include <cuda_runtime.h>
#include <cuda_bf16.h>
#include <mma.h>
#include <cstdint>

using namespace nvcuda;

#define N_NODES 50000
#define N_EDGES 640000
#define D 128
#define KTOT 384          // concat width: [nfeats | sum_n/c | sum_e/c]
#define M_PAD 50048       // 391 * 128, GEMM M padding
#define N_TILES (M_PAD / 128)         // 391
#define GRID_GEMM 296     // 148 SMs x 2 CTAs -> single balanced wave
#define NBLK_SCAN 49      // ceil(50000 / 1024)

#define BK 32             // K chunk
#define ASTR 40           // smem operand stride (bf16 elems) -> 80B, conflict-free ldmatrix
#define CSTR 132          // smem C stride (f32)
// double-buffered operand stages: 4 ops x 128 x ASTR x 2B = 40960 per stage
#define OPB   (128 * ASTR * 2)
#define STAGE (4 * OPB)
#define SMEM_BYTES (2 * STAGE)        // 81920 >= C reuse (128*CSTR*4 = 67584)

// ---------------- scratch (static __device__ globals; no allocs) -------------
__device__ int       g_cnt[N_NODES];  // .bss zero; self-cleaned by scan3 each run
__device__ int       g_off[N_NODES + 1];
__device__ int       g_cur[N_NODES];
__device__ long long g_edge[N_EDGES]; // packed (src << 32) | eid
__device__ int       g_bsum[64];
__device__ float     g_flag[N_NODES]; // 1.0 if node has >=1 in-edge
__device__ float     g_bias2[D];      // Wa2 @ b_msg
// bf16 two-term split operands for the tensor-core GEMM
__device__ __nv_bfloat16 g_Ahi[(size_t)M_PAD * KTOT];  // pad rows stay 0 (.bss)
__device__ __nv_bfloat16 g_Alo[(size_t)M_PAD * KTOT];
__device__ __nv_bfloat16 g_Bhi[D * KTOT];              // [n][k] K-major
__device__ __nv_bfloat16 g_Blo[D * KTOT];

// ---------------- bf16 split helpers ----------------------------------------
__device__ __forceinline__ uint2 pack_bf4(float a, float b, float c, float d) {
    __nv_bfloat162 p0 = __floats2bfloat162_rn(a, b);
    __nv_bfloat162 p1 = __floats2bfloat162_rn(c, d);
    uint2 r;
    r.x = *(unsigned*)&p0;
    r.y = *(unsigned*)&p1;
    return r;
}
__device__ __forceinline__ float bf_res(float x) {   // residual after bf16 round
    return x - __bfloat162float(__float2bfloat16_rn(x));
}

// ---------------- cp.async helpers ------------------------------------------
__device__ __forceinline__ void cp16(void* dst_smem, const void* src) {
    uint32_t s = (uint32_t)__cvta_generic_to_shared(dst_smem);
    asm volatile("cp.async.ca.shared.global [%0], [%1], 16;" :: "r"(s), "l"(src));
}
__device__ __forceinline__ void cp_commit() { asm volatile("cp.async.commit_group;" ::: "memory"); }
__device__ __forceinline__ void cp_wait1()  { asm volatile("cp.async.wait_group 1;" ::: "memory"); }
__device__ __forceinline__ void cp_wait0()  { asm volatile("cp.async.wait_group 0;" ::: "memory"); }

// ---------------- K1: weight composition -> bf16 hi/lo B --------------------
__global__ void wc_kernel(const float* __restrict__ Wm,
                          const float* __restrict__ bm,
                          const float* __restrict__ Wa) {
    __shared__ float wa2[128];
    int o = blockIdx.x;           // 0..127 (output col n)
    int t = threadIdx.x;          // 0..255
    if (t < 128) wa2[t] = Wa[o * 256 + 128 + t];
    __syncthreads();
    if (t < 128) {
        float v = Wa[o * 256 + t];
        g_Bhi[o * KTOT + t] = __float2bfloat16_rn(v);
        g_Blo[o * KTOT + t] = __float2bfloat16_rn(bf_res(v));
    }
    float s = 0.f;
#pragma unroll 4
    for (int j = 0; j < 128; j++) s += wa2[j] * Wm[j * 256 + t];
    g_Bhi[o * KTOT + 128 + t] = __float2bfloat16_rn(s);
    g_Blo[o * KTOT + 128 + t] = __float2bfloat16_rn(bf_res(s));
    if (t == 0) {
        float b = 0.f;
        for (int j = 0; j < 128; j++) b += wa2[j] * bm[j];
        g_bias2[o] = b;
    }
}

// ---------------- K2: histogram dst (g_cnt is pre-zeroed invariant) ---------
__global__ void count_kernel(const int* __restrict__ dst) {
    int i = blockIdx.x * blockDim.x + threadIdx.x;
    if (i < N_EDGES) atomicAdd(&g_cnt[__ldg(&dst[i])], 1);
}

// ---------------- K3a: per-block scan (49 blocks x 1024) --------------------
__global__ void scan1_kernel() {
    __shared__ int wsum[32];
    int t = threadIdx.x;
    int i = blockIdx.x * 1024 + t;
    int v = (i < N_NODES) ? g_cnt[i] : 0;
    int x = v;
#pragma unroll
    for (int o = 1; o < 32; o <<= 1) {
        int y = __shfl_up_sync(0xFFFFFFFFu, x, o);
        if ((t & 31) >= o) x += y;
    }
    if ((t & 31) == 31) wsum[t >> 5] = x;
    __syncthreads();
    if (t < 32) {
        int w = wsum[t];
#pragma unroll
        for (int o = 1; o < 32; o <<= 1) {
            int y = __shfl_up_sync(0xFFFFFFFFu, w, o);
            if (t >= o) w += y;
        }
        wsum[t] = w;
    }
    __syncthreads();
    int warp = t >> 5;
    int excl = x - v + (warp ? wsum[warp - 1] : 0);
    if (i < N_NODES) g_off[i] = excl;
    if (t == 1023) g_bsum[blockIdx.x] = wsum[31];
}

// ---------------- K3b: finalize offsets (merged 49-sum scan), cursors -------
// Every block redundantly scans the 49 block sums in its first warp (cheap,
// hidden) -> no separate scan2 launch. Also self-cleans g_cnt.
__global__ void scan3_kernel() {
    __shared__ int s_bpre[64];
    int t = threadIdx.x;
    if (t < 32) {
        int a = g_bsum[t];
        int b = (32 + t < NBLK_SCAN) ? g_bsum[32 + t] : 0;
        int ia = a, ib = b;
#pragma unroll
        for (int o = 1; o < 32; o <<= 1) {
            int ya = __shfl_up_sync(0xFFFFFFFFu, ia, o);
            int yb = __shfl_up_sync(0xFFFFFFFFu, ib, o);
            if (t >= o) { ia += ya; ib += yb; }
        }
        int tot = __shfl_sync(0xFFFFFFFFu, ia, 31);
        s_bpre[t] = ia - a;
        if (32 + t < 64) s_bpre[32 + t] = tot + ib - b;
    }
    __syncthreads();
    int i = blockIdx.x * blockDim.x + t;
    if (i < N_NODES) {
        int o = g_off[i] + s_bpre[i >> 10];
        g_off[i] = o;
        g_cur[i] = o;
        g_cnt[i] = 0;              // restore the zero invariant for the next run
    }
    if (i == 0) g_off[N_NODES] = N_EDGES;
}

// ---------------- K4: fill CSR with packed (src, eid) records ---------------
__global__ void fill_kernel(const int* __restrict__ dst, const int* __restrict__ src) {
    int i = blockIdx.x * blockDim.x + threadIdx.x;
    if (i < N_EDGES) {
        int v = __ldg(&dst[i]);
        int p = atomicAdd(&g_cur[v], 1);
        long long rec = ((long long)(unsigned)__ldg(&src[i]) << 32) | (unsigned)i;
        g_edge[p] = rec;
    }
}

// ---------------- K5: gather-sum with lane-parallel record prefetch ---------
// Warp per node. Lanes cooperatively load up to 32 packed (src,eid) records in
// one coalesced 8B round; broadcast via 64-bit shfl; feature loads then have
// register-resident addresses -> deep MLP.
__global__ void gather_kernel(const float* __restrict__ nfeats,
                              const float* __restrict__ efeats) {
    int node = (blockIdx.x * blockDim.x + threadIdx.x) >> 5;
    int lane = threadIdx.x & 31;
    if (node >= N_NODES) return;
    int s = g_off[node];
    int e = g_off[node + 1];
    float4 an = make_float4(0.f, 0.f, 0.f, 0.f);
    float4 ae = make_float4(0.f, 0.f, 0.f, 0.f);

    for (int base = s; base < e; base += 32) {
        int p = base + lane;
        long long my_rec = 0;
        if (p < e) my_rec = __ldcs(&g_edge[p]);   // coalesced 8B, evict-first
        int cnt = min(32, e - base);
#pragma unroll 8
        for (int j = 0; j < cnt; j++) {
            long long rec = __shfl_sync(0xFFFFFFFFu, my_rec, j);
            int eid_j = (int)(unsigned)rec;
            int sv_j  = (int)(rec >> 32);
            float4 nv = __ldg (((const float4*)(nfeats + (size_t)sv_j  * D)) + lane); // L2-resident
            float4 ev = __ldcs(((const float4*)(efeats + (size_t)eid_j * D)) + lane); // stream
            an.x += nv.x; an.y += nv.y; an.z += nv.z; an.w += nv.w;
            ae.x += ev.x; ae.y += ev.y; ae.z += ev.z; ae.w += ev.w;
        }
    }

    float inv = 1.0f / (float)max(e - s, 1);
    an.x *= inv; an.y *= inv; an.z *= inv; an.w *= inv;
    ae.x *= inv; ae.y *= inv; ae.z *= inv; ae.w *= inv;
    float4 nf = ((const float4*)(nfeats + (size_t)node * D))[lane];

    size_t base = (size_t)node * KTOT + lane * 4;
    float4 segs[3] = { nf, an, ae };
#pragma unroll
    for (int sgi = 0; sgi < 3; sgi++) {
        float4 v = segs[sgi];
        *(uint2*)(g_Ahi + base + sgi * 128) = pack_bf4(v.x, v.y, v.z, v.w);
        *(uint2*)(g_Alo + base + sgi * 128) =
            pack_bf4(bf_res(v.x), bf_res(v.y), bf_res(v.z), bf_res(v.w));
    }
    if (lane == 0) g_flag[node] = (e > s) ? 1.0f : 0.0f;
}

// ---------------- K6: wmma bf16-split GEMM, cp.async 2-stage, persistent ----
// Grid = 296 CTAs (one balanced wave at 2 CTAs/SM); each strides over tiles.
__global__ __launch_bounds__(256, 2) void gemm_wmma_kernel(const float* __restrict__ bias_a,
                                                           float* __restrict__ out) {
    extern __shared__ char smem[];
    float* sC = (float*)smem;

    const int tid = threadIdx.x;
    const int wid = tid >> 5;
    const int wr  = wid >> 1;       // 0..3 -> rows wr*32..+31
    const int wc  = wid & 1;        // 0..1 -> cols wc*64..+63

    const int lrow = tid >> 2;            // 0..63
    const int lg   = (tid & 3) * 8;       // bf16 granule offset

    for (int tile = blockIdx.x; tile < N_TILES; tile += GRID_GEMM) {
        const int m0 = tile * 128;

        auto load_chunk = [&](int kc, int stage) {
            char* sb = smem + stage * STAGE;
#pragma unroll
            for (int half = 0; half < 2; half++) {
                int row = lrow + half * 64;
                size_t ga = (size_t)(m0 + row) * KTOT + kc + lg;
                size_t gb = (size_t)row * KTOT + kc + lg;
                uint32_t so = (row * ASTR + lg) * 2;
                cp16(sb + 0 * OPB + so, g_Ahi + ga);
                cp16(sb + 1 * OPB + so, g_Alo + ga);
                cp16(sb + 2 * OPB + so, g_Bhi + gb);
                cp16(sb + 3 * OPB + so, g_Blo + gb);
            }
            cp_commit();
        };

        wmma::fragment<wmma::accumulator, 16, 16, 16, float> c[2][4];
#pragma unroll
        for (int mi = 0; mi < 2; mi++)
#pragma unroll
            for (int ni = 0; ni < 4; ni++) wmma::fill_fragment(c[mi][ni], 0.f);

        load_chunk(0, 0);

        const int NCH = KTOT / BK;      // 12
#pragma unroll 1
        for (int i = 0; i < NCH; i++) {
            if (i + 1 < NCH) { load_chunk((i + 1) * BK, (i + 1) & 1); cp_wait1(); }
            else             { cp_wait0(); }
            __syncthreads();

            char* sb = smem + (i & 1) * STAGE;
            __nv_bfloat16* sAhi = (__nv_bfloat16*)(sb + 0 * OPB);
            __nv_bfloat16* sAlo = (__nv_bfloat16*)(sb + 1 * OPB);
            __nv_bfloat16* sBhi = (__nv_bfloat16*)(sb + 2 * OPB);
            __nv_bfloat16* sBlo = (__nv_bfloat16*)(sb + 3 * OPB);

#pragma unroll
            for (int ks = 0; ks < BK / 16; ks++) {
                wmma::fragment<wmma::matrix_a, 16, 16, 16, __nv_bfloat16, wmma::row_major> ah[2], al[2];
#pragma unroll
                for (int mi = 0; mi < 2; mi++) {
                    wmma::load_matrix_sync(ah[mi], sAhi + (wr * 32 + mi * 16) * ASTR + ks * 16, ASTR);
                    wmma::load_matrix_sync(al[mi], sAlo + (wr * 32 + mi * 16) * ASTR + ks * 16, ASTR);
                }
#pragma unroll
                for (int ni = 0; ni < 4; ni++) {
                    wmma::fragment<wmma::matrix_b, 16, 16, 16, __nv_bfloat16, wmma::col_major> bh, bl;
                    wmma::load_matrix_sync(bh, sBhi + (wc * 64 + ni * 16) * ASTR + ks * 16, ASTR);
                    wmma::load_matrix_sync(bl, sBlo + (wc * 64 + ni * 16) * ASTR + ks * 16, ASTR);
#pragma unroll
                    for (int mi = 0; mi < 2; mi++) {
                        wmma::mma_sync(c[mi][ni], ah[mi], bh, c[mi][ni]);
                        wmma::mma_sync(c[mi][ni], ah[mi], bl, c[mi][ni]);
                        wmma::mma_sync(c[mi][ni], al[mi], bh, c[mi][ni]);
                    }
                }
            }
            __syncthreads();   // all warps done reading this stage before refill
        }

        // operands dead; reuse smem for C
#pragma unroll
        for (int mi = 0; mi < 2; mi++)
#pragma unroll
            for (int ni = 0; ni < 4; ni++)
                wmma::store_matrix_sync(sC + (wr * 32 + mi * 16) * CSTR + wc * 64 + ni * 16,
                                        c[mi][ni], CSTR, wmma::mem_row_major);
        __syncthreads();

        // epilogue: relu(c + bias_a[n] + flag[m]*bias2[n])
        {
            int row = tid >> 1;
            int ch  = (tid & 1) * 64;
            int m   = m0 + row;
            if (m < N_NODES) {
                float fl = g_flag[m];
                const float* crow = sC + row * CSTR + ch;
#pragma unroll
                for (int c4 = 0; c4 < 64; c4 += 4) {
                    int col = ch + c4;
                    float4 v = *(const float4*)(crow + c4);
                    float v0 = v.x + __ldg(&bias_a[col + 0]) + fl * g_bias2[col + 0];
                    float v1 = v.y + __ldg(&bias_a[col + 1]) + fl * g_bias2[col + 1];
                    float v2 = v.z + __ldg(&bias_a[col + 2]) + fl * g_bias2[col + 2];
                    float v3 = v.w + __ldg(&bias_a[col + 3]) + fl * g_bias2[col + 3];
                    float4 o4;
                    o4.x = v0 > 0.f ? v0 : 0.f;
                    o4.y = v1 > 0.f ? v1 : 0.f;
                    o4.z = v2 > 0.f ? v2 : 0.f;
                    o4.w = v3 > 0.f ? v3 : 0.f;
                    *(float4*)&out[(size_t)m * D + col] = o4;
                }
            }
        }
        __syncthreads();   // sC reads done before next tile's cp.async overwrites
    }
}

// ---------------- launch -----------------------------------------------------
extern "C" void kernel_launch(void* const* d_in, const int* in_sizes, int n_in,
                              void* d_out, int out_size) {
    const float* nfeats = (const float*)d_in[0];
    const float* efeats = (const float*)d_in[1];
    const float* Wm     = (const float*)d_in[2];
    const float* bm     = (const float*)d_in[3];
    const float* Wa     = (const float*)d_in[4];
    const float* ba     = (const float*)d_in[5];
    const int*   src    = (const int*)d_in[6];
    const int*   dst    = (const int*)d_in[7];
    float* out = (float*)d_out;

    cudaFuncSetAttribute(gemm_wmma_kernel,
                         cudaFuncAttributeMaxDynamicSharedMemorySize, SMEM_BYTES);

    wc_kernel    <<<D, 256>>>(Wm, bm, Wa);
    count_kernel <<<(N_EDGES + 255) / 256, 256>>>(dst);
    scan1_kernel <<<NBLK_SCAN, 1024>>>();
    scan3_kernel <<<(N_NODES + 255) / 256, 256>>>();
    fill_kernel  <<<(N_EDGES + 255) / 256, 256>>>(dst, src);
    gather_kernel<<<(N_NODES * 32 + 255) / 256, 256>>>(nfeats, efeats);
    gemm_wmma_kernel<<<GRID_GEMM, 256, SMEM_BYTES>>>(ba, out);
}

// round 15
// speedup vs baseline: 1.2500x; 1.2500x over previous
#include <cuda_runtime.h>
#include <cuda_bf16.h>
#include <mma.h>
#include <cstdint>

using namespace nvcuda;

#define N_NODES 50000
#define N_EDGES 640000
#define D 128
#define KTOT 384          // concat width: [nfeats | sum_n/c | sum_e/c]
#define M_PAD 50048       // 391 * 128, GEMM M padding
#define NBLK_SCAN 49      // ceil(50000 / 1024)

#define BK 32             // K chunk
#define ASTR 40           // smem operand stride (bf16 elems) -> 80B, conflict-free ldmatrix
#define CSTR 132          // smem C stride (f32)
// double-buffered operand stages: 4 ops x 128 x ASTR x 2B = 40960 per stage
#define OPB   (128 * ASTR * 2)
#define STAGE (4 * OPB)
#define SMEM_BYTES (2 * STAGE)        // 81920 >= C reuse (128*CSTR*4 = 67584)

// ---------------- scratch (static __device__ globals; no allocs) -------------
__device__ int   g_cnt[N_NODES];      // .bss zero; self-cleaned by scan3 each run
__device__ int   g_off[N_NODES + 1];
__device__ int   g_cur[N_NODES];
__device__ int   g_eid[N_EDGES];
__device__ int   g_bsum[64];
__device__ float g_flag[N_NODES];     // 1.0 if node has >=1 in-edge
__device__ float g_bias2[D];          // Wa2 @ b_msg
// bf16 two-term split operands for the tensor-core GEMM
__device__ __nv_bfloat16 g_Ahi[(size_t)M_PAD * KTOT];  // pad rows stay 0 (.bss)
__device__ __nv_bfloat16 g_Alo[(size_t)M_PAD * KTOT];
__device__ __nv_bfloat16 g_Bhi[D * KTOT];              // [n][k] K-major
__device__ __nv_bfloat16 g_Blo[D * KTOT];

// ---------------- bf16 split helpers ----------------------------------------
__device__ __forceinline__ uint2 pack_bf4(float a, float b, float c, float d) {
    __nv_bfloat162 p0 = __floats2bfloat162_rn(a, b);
    __nv_bfloat162 p1 = __floats2bfloat162_rn(c, d);
    uint2 r;
    r.x = *(unsigned*)&p0;
    r.y = *(unsigned*)&p1;
    return r;
}
__device__ __forceinline__ float bf_res(float x) {   // residual after bf16 round
    return x - __bfloat162float(__float2bfloat16_rn(x));
}

// ---------------- cp.async helpers ------------------------------------------
__device__ __forceinline__ void cp16(void* dst_smem, const void* src) {
    uint32_t s = (uint32_t)__cvta_generic_to_shared(dst_smem);
    asm volatile("cp.async.ca.shared.global [%0], [%1], 16;" :: "r"(s), "l"(src));
}
__device__ __forceinline__ void cp_commit() { asm volatile("cp.async.commit_group;" ::: "memory"); }
__device__ __forceinline__ void cp_wait1()  { asm volatile("cp.async.wait_group 1;" ::: "memory"); }
__device__ __forceinline__ void cp_wait0()  { asm volatile("cp.async.wait_group 0;" ::: "memory"); }

// ---------------- K1: weight composition -> bf16 hi/lo B --------------------
__global__ void wc_kernel(const float* __restrict__ Wm,
                          const float* __restrict__ bm,
                          const float* __restrict__ Wa) {
    __shared__ float wa2[128];
    int o = blockIdx.x;           // 0..127 (output col n)
    int t = threadIdx.x;          // 0..255
    if (t < 128) wa2[t] = Wa[o * 256 + 128 + t];
    __syncthreads();
    if (t < 128) {
        float v = Wa[o * 256 + t];
        g_Bhi[o * KTOT + t] = __float2bfloat16_rn(v);
        g_Blo[o * KTOT + t] = __float2bfloat16_rn(bf_res(v));
    }
    float s = 0.f;
#pragma unroll 4
    for (int j = 0; j < 128; j++) s += wa2[j] * Wm[j * 256 + t];
    g_Bhi[o * KTOT + 128 + t] = __float2bfloat16_rn(s);
    g_Blo[o * KTOT + 128 + t] = __float2bfloat16_rn(bf_res(s));
    if (t == 0) {
        float b = 0.f;
        for (int j = 0; j < 128; j++) b += wa2[j] * bm[j];
        g_bias2[o] = b;
    }
}

// ---------------- K2: histogram dst (g_cnt is pre-zeroed invariant) ---------
__global__ void count_kernel(const int* __restrict__ dst) {
    int i = blockIdx.x * blockDim.x + threadIdx.x;
    if (i < N_EDGES) atomicAdd(&g_cnt[dst[i]], 1);
}

// ---------------- K3a: per-block scan (49 blocks x 1024) --------------------
__global__ void scan1_kernel() {
    __shared__ int wsum[32];
    int t = threadIdx.x;
    int i = blockIdx.x * 1024 + t;
    int v = (i < N_NODES) ? g_cnt[i] : 0;
    int x = v;
#pragma unroll
    for (int o = 1; o < 32; o <<= 1) {
        int y = __shfl_up_sync(0xFFFFFFFFu, x, o);
        if ((t & 31) >= o) x += y;
    }
    if ((t & 31) == 31) wsum[t >> 5] = x;
    __syncthreads();
    if (t < 32) {
        int w = wsum[t];
#pragma unroll
        for (int o = 1; o < 32; o <<= 1) {
            int y = __shfl_up_sync(0xFFFFFFFFu, w, o);
            if (t >= o) w += y;
        }
        wsum[t] = w;
    }
    __syncthreads();
    int warp = t >> 5;
    int excl = x - v + (warp ? wsum[warp - 1] : 0);
    if (i < N_NODES) g_off[i] = excl;
    if (t == 1023) g_bsum[blockIdx.x] = wsum[31];
}

// ---------------- K3b: finalize offsets (merged 49-sum scan), cursors -------
// Every block redundantly scans the 49 block sums in its first warp (cheap,
// hidden behind launch) -> no separate scan2 launch. Also self-cleans g_cnt.
__global__ void scan3_kernel() {
    __shared__ int s_bpre[64];
    int t = threadIdx.x;
    if (t < 32) {
        int a = g_bsum[t];
        int b = (32 + t < NBLK_SCAN) ? g_bsum[32 + t] : 0;
        int ia = a, ib = b;
#pragma unroll
        for (int o = 1; o < 32; o <<= 1) {
            int ya = __shfl_up_sync(0xFFFFFFFFu, ia, o);
            int yb = __shfl_up_sync(0xFFFFFFFFu, ib, o);
            if (t >= o) { ia += ya; ib += yb; }
        }
        int tot = __shfl_sync(0xFFFFFFFFu, ia, 31);
        s_bpre[t] = ia - a;
        if (32 + t < 64) s_bpre[32 + t] = tot + ib - b;
    }
    __syncthreads();
    int i = blockIdx.x * blockDim.x + t;
    if (i < N_NODES) {
        int o = g_off[i] + s_bpre[i >> 10];
        g_off[i] = o;
        g_cur[i] = o;
        g_cnt[i] = 0;              // restore the zero invariant for the next run
    }
    if (i == 0) g_off[N_NODES] = N_EDGES;
}

// ---------------- K4: fill CSR edge lists -----------------------------------
__global__ void fill_kernel(const int* __restrict__ dst) {
    int i = blockIdx.x * blockDim.x + threadIdx.x;
    if (i < N_EDGES) {
        int v = dst[i];
        int p = atomicAdd(&g_cur[v], 1);
        g_eid[p] = i;
    }
}

// ---------------- K5: gather-sum with lane-parallel index prefetch ----------
__global__ void gather_kernel(const float* __restrict__ nfeats,
                              const float* __restrict__ efeats,
                              const int* __restrict__ src) {
    int node = (blockIdx.x * blockDim.x + threadIdx.x) >> 5;
    int lane = threadIdx.x & 31;
    if (node >= N_NODES) return;
    int s = g_off[node];
    int e = g_off[node + 1];
    float4 an = make_float4(0.f, 0.f, 0.f, 0.f);
    float4 ae = make_float4(0.f, 0.f, 0.f, 0.f);

    for (int base = s; base < e; base += 32) {
        int p = base + lane;
        int my_eid = 0, my_src = 0;
        if (p < e) {
            my_eid = g_eid[p];            // coalesced: consecutive lanes, consecutive p
            my_src = __ldg(&src[my_eid]); // parallel across lanes
        }
        int cnt = min(32, e - base);
#pragma unroll 8
        for (int j = 0; j < cnt; j++) {
            int eid_j = __shfl_sync(0xFFFFFFFFu, my_eid, j);
            int sv_j  = __shfl_sync(0xFFFFFFFFu, my_src, j);
            float4 nv = __ldg (((const float4*)(nfeats + (size_t)sv_j  * D)) + lane); // L2-resident
            float4 ev = __ldcs(((const float4*)(efeats + (size_t)eid_j * D)) + lane); // stream
            an.x += nv.x; an.y += nv.y; an.z += nv.z; an.w += nv.w;
            ae.x += ev.x; ae.y += ev.y; ae.z += ev.z; ae.w += ev.w;
        }
    }

    float inv = 1.0f / (float)max(e - s, 1);
    an.x *= inv; an.y *= inv; an.z *= inv; an.w *= inv;
    ae.x *= inv; ae.y *= inv; ae.z *= inv; ae.w *= inv;
    float4 nf = ((const float4*)(nfeats + (size_t)node * D))[lane];

    size_t base = (size_t)node * KTOT + lane * 4;
    float4 segs[3] = { nf, an, ae };
#pragma unroll
    for (int sgi = 0; sgi < 3; sgi++) {
        float4 v = segs[sgi];
        *(uint2*)(g_Ahi + base + sgi * 128) = pack_bf4(v.x, v.y, v.z, v.w);
        *(uint2*)(g_Alo + base + sgi * 128) =
            pack_bf4(bf_res(v.x), bf_res(v.y), bf_res(v.z), bf_res(v.w));
    }
    if (lane == 0) g_flag[node] = (e > s) ? 1.0f : 0.0f;
}

// ---------------- K6: wmma bf16-split GEMM, cp.async double-buffered --------
// CTA = 128x128 tile (one per CTA, grid 391), 8 warps (4x2), warp tile 32x64.
__global__ __launch_bounds__(256, 2) void gemm_wmma_kernel(const float* __restrict__ bias_a,
                                                           float* __restrict__ out) {
    extern __shared__ char smem[];
    float* sC = (float*)smem;

    const int tid = threadIdx.x;
    const int wid = tid >> 5;
    const int wr  = wid >> 1;       // 0..3 -> rows wr*32..+31
    const int wc  = wid & 1;        // 0..1 -> cols wc*64..+63
    const int m0  = blockIdx.x * 128;

    const int lrow = tid >> 2;            // 0..63
    const int lg   = (tid & 3) * 8;       // bf16 granule offset

    auto load_chunk = [&](int kc, int stage) {
        char* sb = smem + stage * STAGE;
#pragma unroll
        for (int half = 0; half < 2; half++) {
            int row = lrow + half * 64;
            size_t ga = (size_t)(m0 + row) * KTOT + kc + lg;
            size_t gb = (size_t)row * KTOT + kc + lg;
            uint32_t so = (row * ASTR + lg) * 2;
            cp16(sb + 0 * OPB + so, g_Ahi + ga);
            cp16(sb + 1 * OPB + so, g_Alo + ga);
            cp16(sb + 2 * OPB + so, g_Bhi + gb);
            cp16(sb + 3 * OPB + so, g_Blo + gb);
        }
        cp_commit();
    };

    wmma::fragment<wmma::accumulator, 16, 16, 16, float> c[2][4];
#pragma unroll
    for (int mi = 0; mi < 2; mi++)
#pragma unroll
        for (int ni = 0; ni < 4; ni++) wmma::fill_fragment(c[mi][ni], 0.f);

    load_chunk(0, 0);

    const int NCH = KTOT / BK;      // 12
#pragma unroll 1
    for (int i = 0; i < NCH; i++) {
        if (i + 1 < NCH) { load_chunk((i + 1) * BK, (i + 1) & 1); cp_wait1(); }
        else             { cp_wait0(); }
        __syncthreads();

        char* sb = smem + (i & 1) * STAGE;
        __nv_bfloat16* sAhi = (__nv_bfloat16*)(sb + 0 * OPB);
        __nv_bfloat16* sAlo = (__nv_bfloat16*)(sb + 1 * OPB);
        __nv_bfloat16* sBhi = (__nv_bfloat16*)(sb + 2 * OPB);
        __nv_bfloat16* sBlo = (__nv_bfloat16*)(sb + 3 * OPB);

#pragma unroll
        for (int ks = 0; ks < BK / 16; ks++) {
            wmma::fragment<wmma::matrix_a, 16, 16, 16, __nv_bfloat16, wmma::row_major> ah[2], al[2];
#pragma unroll
            for (int mi = 0; mi < 2; mi++) {
                wmma::load_matrix_sync(ah[mi], sAhi + (wr * 32 + mi * 16) * ASTR + ks * 16, ASTR);
                wmma::load_matrix_sync(al[mi], sAlo + (wr * 32 + mi * 16) * ASTR + ks * 16, ASTR);
            }
#pragma unroll
            for (int ni = 0; ni < 4; ni++) {
                wmma::fragment<wmma::matrix_b, 16, 16, 16, __nv_bfloat16, wmma::col_major> bh, bl;
                wmma::load_matrix_sync(bh, sBhi + (wc * 64 + ni * 16) * ASTR + ks * 16, ASTR);
                wmma::load_matrix_sync(bl, sBlo + (wc * 64 + ni * 16) * ASTR + ks * 16, ASTR);
#pragma unroll
                for (int mi = 0; mi < 2; mi++) {
                    wmma::mma_sync(c[mi][ni], ah[mi], bh, c[mi][ni]);
                    wmma::mma_sync(c[mi][ni], ah[mi], bl, c[mi][ni]);
                    wmma::mma_sync(c[mi][ni], al[mi], bh, c[mi][ni]);
                }
            }
        }
        __syncthreads();   // all warps done reading this stage before it is refilled
    }

    // operands dead; reuse smem for C
#pragma unroll
    for (int mi = 0; mi < 2; mi++)
#pragma unroll
        for (int ni = 0; ni < 4; ni++)
            wmma::store_matrix_sync(sC + (wr * 32 + mi * 16) * CSTR + wc * 64 + ni * 16,
                                    c[mi][ni], CSTR, wmma::mem_row_major);
    __syncthreads();

    // epilogue: relu(c + bias_a[n] + flag[m]*bias2[n]); thread = (row, 64-col half)
    {
        int row = tid >> 1;
        int ch  = (tid & 1) * 64;
        int m   = m0 + row;
        if (m < N_NODES) {
            float fl = g_flag[m];
            const float* crow = sC + row * CSTR + ch;
#pragma unroll
            for (int c4 = 0; c4 < 64; c4 += 4) {
                int col = ch + c4;
                float4 v = *(const float4*)(crow + c4);
                float v0 = v.x + __ldg(&bias_a[col + 0]) + fl * g_bias2[col + 0];
                float v1 = v.y + __ldg(&bias_a[col + 1]) + fl * g_bias2[col + 1];
                float v2 = v.z + __ldg(&bias_a[col + 2]) + fl * g_bias2[col + 2];
                float v3 = v.w + __ldg(&bias_a[col + 3]) + fl * g_bias2[col + 3];
                float4 o4;
                o4.x = v0 > 0.f ? v0 : 0.f;
                o4.y = v1 > 0.f ? v1 : 0.f;
                o4.z = v2 > 0.f ? v2 : 0.f;
                o4.w = v3 > 0.f ? v3 : 0.f;
                *(float4*)&out[(size_t)m * D + col] = o4;
            }
        }
    }
}

// ---------------- launch -----------------------------------------------------
extern "C" void kernel_launch(void* const* d_in, const int* in_sizes, int n_in,
                              void* d_out, int out_size) {
    const float* nfeats = (const float*)d_in[0];
    const float* efeats = (const float*)d_in[1];
    const float* Wm     = (const float*)d_in[2];
    const float* bm     = (const float*)d_in[3];
    const float* Wa     = (const float*)d_in[4];
    const float* ba     = (const float*)d_in[5];
    const int*   src    = (const int*)d_in[6];
    const int*   dst    = (const int*)d_in[7];
    float* out = (float*)d_out;

    cudaFuncSetAttribute(gemm_wmma_kernel,
                         cudaFuncAttributeMaxDynamicSharedMemorySize, SMEM_BYTES);

    wc_kernel    <<<D, 256>>>(Wm, bm, Wa);
    count_kernel <<<(N_EDGES + 255) / 256, 256>>>(dst);
    scan1_kernel <<<NBLK_SCAN, 1024>>>();
    scan3_kernel <<<(N_NODES + 255) / 256, 256>>>();
    fill_kernel  <<<(N_EDGES + 255) / 256, 256>>>(dst);
    gather_kernel<<<(N_NODES * 32 + 255) / 256, 256>>>(nfeats, efeats, src);
    gemm_wmma_kernel<<<M_PAD / 128, 256, SMEM_BYTES>>>(ba, out);
}

// round 17
// speedup vs baseline: 1.4668x; 1.1735x over previous
#include <cuda_runtime.h>
#include <cuda_fp16.h>
#include <mma.h>
#include <cstdint>

using namespace nvcuda;

#define N_NODES 50000
#define N_EDGES 640000
#define D 128
#define KTOT 384          // concat width: [nfeats | sum_n/c | sum_e/c]
#define M_PAD 50048       // 391 * 128, GEMM M padding
#define NBLK_SCAN 49      // ceil(50000 / 1024)

#define BK 32             // K chunk
#define ASTR 40           // smem operand stride (fp16 elems) -> 80B, conflict-free ldmatrix
#define CSTR 132          // smem C stride (f32)
// double-buffered operand stages: 3 ops (A, Bhi, Blo) x 128 x ASTR x 2B
#define OPB   (128 * ASTR * 2)
#define STAGE (3 * OPB)
#define SMEM_BYTES (128 * CSTR * 4)   // 67584 >= 2*STAGE (61440)

// ---------------- scratch (static __device__ globals; no allocs) -------------
__device__ int   g_cnt[N_NODES];      // .bss zero; self-cleaned by scan3 each run
__device__ int   g_off[N_NODES + 1];
__device__ int   g_cur[N_NODES];
__device__ int   g_eid[N_EDGES];
__device__ int   g_bsum[64];
__device__ float g_flag[N_NODES];     // 1.0 if node has >=1 in-edge
__device__ float g_bias2[D];          // Wa2 @ b_msg
// fp16 operands: A single-rounded, B two-term split (error ~ a_res*b ~ 3e-4)
__device__ __half g_A[(size_t)M_PAD * KTOT];   // pad rows stay 0 (.bss)
__device__ __half g_Bhi[D * KTOT];             // [n][k] K-major
__device__ __half g_Blo[D * KTOT];

// ---------------- fp16 pack helpers -----------------------------------------
__device__ __forceinline__ uint2 pack_hf4(float a, float b, float c, float d) {
    __half2 p0 = __floats2half2_rn(a, b);
    __half2 p1 = __floats2half2_rn(c, d);
    uint2 r;
    r.x = *(unsigned*)&p0;
    r.y = *(unsigned*)&p1;
    return r;
}

// ---------------- cp.async helpers ------------------------------------------
__device__ __forceinline__ void cp16(void* dst_smem, const void* src) {
    uint32_t s = (uint32_t)__cvta_generic_to_shared(dst_smem);
    asm volatile("cp.async.ca.shared.global [%0], [%1], 16;" :: "r"(s), "l"(src));
}
__device__ __forceinline__ void cp_commit() { asm volatile("cp.async.commit_group;" ::: "memory"); }
__device__ __forceinline__ void cp_wait1()  { asm volatile("cp.async.wait_group 1;" ::: "memory"); }
__device__ __forceinline__ void cp_wait0()  { asm volatile("cp.async.wait_group 0;" ::: "memory"); }

// ---------------- K1: weight composition -> fp16 hi/lo B --------------------
__global__ void wc_kernel(const float* __restrict__ Wm,
                          const float* __restrict__ bm,
                          const float* __restrict__ Wa) {
    __shared__ float wa2[128];
    int o = blockIdx.x;           // 0..127 (output col n)
    int t = threadIdx.x;          // 0..255
    if (t < 128) wa2[t] = Wa[o * 256 + 128 + t];
    __syncthreads();
    if (t < 128) {
        float v = Wa[o * 256 + t];
        __half h = __float2half_rn(v);
        g_Bhi[o * KTOT + t] = h;
        g_Blo[o * KTOT + t] = __float2half_rn(v - __half2float(h));
    }
    float s = 0.f;
#pragma unroll 4
    for (int j = 0; j < 128; j++) s += wa2[j] * Wm[j * 256 + t];
    {
        __half h = __float2half_rn(s);
        g_Bhi[o * KTOT + 128 + t] = h;
        g_Blo[o * KTOT + 128 + t] = __float2half_rn(s - __half2float(h));
    }
    if (t == 0) {
        float b = 0.f;
        for (int j = 0; j < 128; j++) b += wa2[j] * bm[j];
        g_bias2[o] = b;
    }
}

// ---------------- K2: histogram dst (g_cnt is pre-zeroed invariant) ---------
__global__ void count_kernel(const int* __restrict__ dst) {
    int i = blockIdx.x * blockDim.x + threadIdx.x;
    if (i < N_EDGES) atomicAdd(&g_cnt[dst[i]], 1);
}

// ---------------- K3a: per-block scan (49 blocks x 1024) --------------------
__global__ void scan1_kernel() {
    __shared__ int wsum[32];
    int t = threadIdx.x;
    int i = blockIdx.x * 1024 + t;
    int v = (i < N_NODES) ? g_cnt[i] : 0;
    int x = v;
#pragma unroll
    for (int o = 1; o < 32; o <<= 1) {
        int y = __shfl_up_sync(0xFFFFFFFFu, x, o);
        if ((t & 31) >= o) x += y;
    }
    if ((t & 31) == 31) wsum[t >> 5] = x;
    __syncthreads();
    if (t < 32) {
        int w = wsum[t];
#pragma unroll
        for (int o = 1; o < 32; o <<= 1) {
            int y = __shfl_up_sync(0xFFFFFFFFu, w, o);
            if (t >= o) w += y;
        }
        wsum[t] = w;
    }
    __syncthreads();
    int warp = t >> 5;
    int excl = x - v + (warp ? wsum[warp - 1] : 0);
    if (i < N_NODES) g_off[i] = excl;
    if (t == 1023) g_bsum[blockIdx.x] = wsum[31];
}

// ---------------- K3b: finalize offsets (merged 49-sum scan), cursors -------
__global__ void scan3_kernel() {
    __shared__ int s_bpre[64];
    int t = threadIdx.x;
    if (t < 32) {
        int a = g_bsum[t];
        int b = (32 + t < NBLK_SCAN) ? g_bsum[32 + t] : 0;
        int ia = a, ib = b;
#pragma unroll
        for (int o = 1; o < 32; o <<= 1) {
            int ya = __shfl_up_sync(0xFFFFFFFFu, ia, o);
            int yb = __shfl_up_sync(0xFFFFFFFFu, ib, o);
            if (t >= o) { ia += ya; ib += yb; }
        }
        int tot = __shfl_sync(0xFFFFFFFFu, ia, 31);
        s_bpre[t] = ia - a;
        if (32 + t < 64) s_bpre[32 + t] = tot + ib - b;
    }
    __syncthreads();
    int i = blockIdx.x * blockDim.x + t;
    if (i < N_NODES) {
        int o = g_off[i] + s_bpre[i >> 10];
        g_off[i] = o;
        g_cur[i] = o;
        g_cnt[i] = 0;              // restore the zero invariant for the next run
    }
    if (i == 0) g_off[N_NODES] = N_EDGES;
}

// ---------------- K4: fill CSR edge lists -----------------------------------
__global__ void fill_kernel(const int* __restrict__ dst) {
    int i = blockIdx.x * blockDim.x + threadIdx.x;
    if (i < N_EDGES) {
        int v = dst[i];
        int p = atomicAdd(&g_cur[v], 1);
        g_eid[p] = i;
    }
}

// ---------------- K5: gather-sum with lane-parallel index prefetch ----------
__global__ void gather_kernel(const float* __restrict__ nfeats,
                              const float* __restrict__ efeats,
                              const int* __restrict__ src) {
    int node = (blockIdx.x * blockDim.x + threadIdx.x) >> 5;
    int lane = threadIdx.x & 31;
    if (node >= N_NODES) return;
    int s = g_off[node];
    int e = g_off[node + 1];
    float4 an = make_float4(0.f, 0.f, 0.f, 0.f);
    float4 ae = make_float4(0.f, 0.f, 0.f, 0.f);

    for (int base = s; base < e; base += 32) {
        int p = base + lane;
        int my_eid = 0, my_src = 0;
        if (p < e) {
            my_eid = g_eid[p];            // coalesced: consecutive lanes, consecutive p
            my_src = __ldg(&src[my_eid]); // parallel across lanes
        }
        int cnt = min(32, e - base);
#pragma unroll 8
        for (int j = 0; j < cnt; j++) {
            int eid_j = __shfl_sync(0xFFFFFFFFu, my_eid, j);
            int sv_j  = __shfl_sync(0xFFFFFFFFu, my_src, j);
            float4 nv = __ldg (((const float4*)(nfeats + (size_t)sv_j  * D)) + lane); // L2-resident
            float4 ev = __ldcs(((const float4*)(efeats + (size_t)eid_j * D)) + lane); // stream
            an.x += nv.x; an.y += nv.y; an.z += nv.z; an.w += nv.w;
            ae.x += ev.x; ae.y += ev.y; ae.z += ev.z; ae.w += ev.w;
        }
    }

    float inv = 1.0f / (float)max(e - s, 1);
    an.x *= inv; an.y *= inv; an.z *= inv; an.w *= inv;
    ae.x *= inv; ae.y *= inv; ae.z *= inv; ae.w *= inv;
    float4 nf = ((const float4*)(nfeats + (size_t)node * D))[lane];

    size_t base = (size_t)node * KTOT + lane * 4;
    float4 segs[3] = { nf, an, ae };
#pragma unroll
    for (int sgi = 0; sgi < 3; sgi++) {
        float4 v = segs[sgi];
        *(uint2*)(g_A + base + sgi * 128) = pack_hf4(v.x, v.y, v.z, v.w);
    }
    if (lane == 0) g_flag[node] = (e > s) ? 1.0f : 0.0f;
}

// ---------------- K6: wmma fp16 2-term GEMM, cp.async double-buffered -------
// CTA = 128x128 tile (grid 391), 8 warps (4x2), warp tile 32x64.
// out = relu(A @ (Bhi+Blo)^T + bias); A single fp16, error ~ a_res*b ~ 3e-4.
__global__ __launch_bounds__(256, 2) void gemm_wmma_kernel(const float* __restrict__ bias_a,
                                                           float* __restrict__ out) {
    extern __shared__ char smem[];
    float* sC = (float*)smem;

    const int tid = threadIdx.x;
    const int wid = tid >> 5;
    const int wr  = wid >> 1;       // 0..3 -> rows wr*32..+31
    const int wc  = wid & 1;        // 0..1 -> cols wc*64..+63
    const int m0  = blockIdx.x * 128;

    const int lrow = tid >> 2;            // 0..63
    const int lg   = (tid & 3) * 8;       // fp16 granule offset

    auto load_chunk = [&](int kc, int stage) {
        char* sb = smem + stage * STAGE;
#pragma unroll
        for (int half_i = 0; half_i < 2; half_i++) {
            int row = lrow + half_i * 64;
            size_t ga = (size_t)(m0 + row) * KTOT + kc + lg;
            size_t gb = (size_t)row * KTOT + kc + lg;
            uint32_t so = (row * ASTR + lg) * 2;
            cp16(sb + 0 * OPB + so, g_A   + ga);
            cp16(sb + 1 * OPB + so, g_Bhi + gb);
            cp16(sb + 2 * OPB + so, g_Blo + gb);
        }
        cp_commit();
    };

    wmma::fragment<wmma::accumulator, 16, 16, 16, float> c[2][4];
#pragma unroll
    for (int mi = 0; mi < 2; mi++)
#pragma unroll
        for (int ni = 0; ni < 4; ni++) wmma::fill_fragment(c[mi][ni], 0.f);

    load_chunk(0, 0);

    const int NCH = KTOT / BK;      // 12
#pragma unroll 1
    for (int i = 0; i < NCH; i++) {
        if (i + 1 < NCH) { load_chunk((i + 1) * BK, (i + 1) & 1); cp_wait1(); }
        else             { cp_wait0(); }
        __syncthreads();

        char* sb = smem + (i & 1) * STAGE;
        __half* sA   = (__half*)(sb + 0 * OPB);
        __half* sBhi = (__half*)(sb + 1 * OPB);
        __half* sBlo = (__half*)(sb + 2 * OPB);

#pragma unroll
        for (int ks = 0; ks < BK / 16; ks++) {
            wmma::fragment<wmma::matrix_a, 16, 16, 16, __half, wmma::row_major> a[2];
#pragma unroll
            for (int mi = 0; mi < 2; mi++)
                wmma::load_matrix_sync(a[mi], sA + (wr * 32 + mi * 16) * ASTR + ks * 16, ASTR);
#pragma unroll
            for (int ni = 0; ni < 4; ni++) {
                wmma::fragment<wmma::matrix_b, 16, 16, 16, __half, wmma::col_major> bh, bl;
                wmma::load_matrix_sync(bh, sBhi + (wc * 64 + ni * 16) * ASTR + ks * 16, ASTR);
                wmma::load_matrix_sync(bl, sBlo + (wc * 64 + ni * 16) * ASTR + ks * 16, ASTR);
#pragma unroll
                for (int mi = 0; mi < 2; mi++) {
                    wmma::mma_sync(c[mi][ni], a[mi], bh, c[mi][ni]);
                    wmma::mma_sync(c[mi][ni], a[mi], bl, c[mi][ni]);
                }
            }
        }
        __syncthreads();   // all warps done reading this stage before it is refilled
    }

    // operands dead; reuse smem for C
#pragma unroll
    for (int mi = 0; mi < 2; mi++)
#pragma unroll
        for (int ni = 0; ni < 4; ni++)
            wmma::store_matrix_sync(sC + (wr * 32 + mi * 16) * CSTR + wc * 64 + ni * 16,
                                    c[mi][ni], CSTR, wmma::mem_row_major);
    __syncthreads();

    // epilogue: relu(c + bias_a[n] + flag[m]*bias2[n]); thread = (row, 64-col half)
    {
        int row = tid >> 1;
        int ch  = (tid & 1) * 64;
        int m   = m0 + row;
        if (m < N_NODES) {
            float fl = g_flag[m];
            const float* crow = sC + row * CSTR + ch;
#pragma unroll
            for (int c4 = 0; c4 < 64; c4 += 4) {
                int col = ch + c4;
                float4 v = *(const float4*)(crow + c4);
                float v0 = v.x + __ldg(&bias_a[col + 0]) + fl * g_bias2[col + 0];
                float v1 = v.y + __ldg(&bias_a[col + 1]) + fl * g_bias2[col + 1];
                float v2 = v.z + __ldg(&bias_a[col + 2]) + fl * g_bias2[col + 2];
                float v3 = v.w + __ldg(&bias_a[col + 3]) + fl * g_bias2[col + 3];
                float4 o4;
                o4.x = v0 > 0.f ? v0 : 0.f;
                o4.y = v1 > 0.f ? v1 : 0.f;
                o4.z = v2 > 0.f ? v2 : 0.f;
                o4.w = v3 > 0.f ? v3 : 0.f;
                *(float4*)&out[(size_t)m * D + col] = o4;
            }
        }
    }
}

// ---------------- launch -----------------------------------------------------
extern "C" void kernel_launch(void* const* d_in, const int* in_sizes, int n_in,
                              void* d_out, int out_size) {
    const float* nfeats = (const float*)d_in[0];
    const float* efeats = (const float*)d_in[1];
    const float* Wm     = (const float*)d_in[2];
    const float* bm     = (const float*)d_in[3];
    const float* Wa     = (const float*)d_in[4];
    const float* ba     = (const float*)d_in[5];
    const int*   src    = (const int*)d_in[6];
    const int*   dst    = (const int*)d_in[7];
    float* out = (float*)d_out;

    cudaFuncSetAttribute(gemm_wmma_kernel,
                         cudaFuncAttributeMaxDynamicSharedMemorySize, SMEM_BYTES);

    wc_kernel    <<<D, 256>>>(Wm, bm, Wa);
    count_kernel <<<(N_EDGES + 255) / 256, 256>>>(dst);
    scan1_kernel <<<NBLK_SCAN, 1024>>>();
    scan3_kernel <<<(N_NODES + 255) / 256, 256>>>();
    fill_kernel  <<<(N_EDGES + 255) / 256, 256>>>(dst);
    gather_kernel<<<(N_NODES * 32 + 255) / 256, 256>>>(nfeats, efeats, src);
    gemm_wmma_kernel<<<M_PAD / 128, 256, SMEM_BYTES>>>(ba, out);
}